// round 13
// baseline (speedup 1.0000x reference)
#include <cuda_runtime.h>
#include <cuda_fp16.h>

#define MAX_NODES 50000
#define MAX_EDGES 800000
#define CH 128
#define OUTC 64
#define BUCKET 64   // per-node edge bucket capacity (Poisson(16): overflow prob ~1e-18)

// ---- device scratch ----
__device__ __half g_H[MAX_NODES * CH];       // fp16(x @ W1)
__device__ __half g_hidden[MAX_NODES * CH];  // fp16(relu(A_hat@H+b1))
__device__ int    g_deg[MAX_NODES];          // self-restoring: zeroed by k_gather_gemm2
__device__ float  g_dinv[MAX_NODES];
__device__ int    g_cursor[MAX_NODES];       // self-restoring: zeroed by k_dinv
__device__ int2   g_edge[MAX_NODES * BUCKET]; // bucketed edges {src, nrm}

// ---------------- mma / ldmatrix macros ----------------
#define LDSM_X4(r0, r1, r2, r3, addr) \
    asm volatile("ldmatrix.sync.aligned.m8n8.x4.shared.b16 {%0,%1,%2,%3}, [%4];" \
                 : "=r"(r0), "=r"(r1), "=r"(r2), "=r"(r3) : "r"(addr))
#define LDSM_X4_T(r0, r1, r2, r3, addr) \
    asm volatile("ldmatrix.sync.aligned.m8n8.x4.trans.shared.b16 {%0,%1,%2,%3}, [%4];" \
                 : "=r"(r0), "=r"(r1), "=r"(r2), "=r"(r3) : "r"(addr))
#define MMA16816(c0, c1, c2, c3, a0, a1, a2, a3, b0, b1) \
    asm volatile("mma.sync.aligned.m16n8k16.row.col.f32.f16.f16.f32 " \
                 "{%0,%1,%2,%3}, {%4,%5,%6,%7}, {%8,%9}, {%0,%1,%2,%3};" \
                 : "+f"(c0), "+f"(c1), "+f"(c2), "+f"(c3) \
                 : "r"(a0), "r"(a1), "r"(a2), "r"(a3), "r"(b0), "r"(b1))

// XOR swizzle for 256B rows (128 halves): conflict-free ldmatrix.
__device__ __forceinline__ int swz(int row, int colh) {
    int chunk = colh >> 3;
    chunk = (chunk & 8) | ((chunk ^ row) & 7);
    return row * 128 + chunk * 8 + (colh & 7);
}

// Per-block int64-vs-int32 edge dtype detection (odd words all zero => int64).
__device__ __forceinline__ int detect_is64(const void* ei) {
    __shared__ int s_is64;
    if (threadIdx.x < 32) {
        int w = ((const int*)ei)[2 * threadIdx.x + 1];
        unsigned m = __ballot_sync(~0u, w == 0);
        if (threadIdx.x == 0) s_is64 = (m == ~0u);
    }
    __syncthreads();
    return s_is64;
}

__device__ __forceinline__ int edge_at(const void* ei, int i, int is64) {
    if (is64) return (int)((const long long*)ei)[i];
    return ((const int*)ei)[i];
}

// ---------------- degree count (g_deg starts zeroed: load-init / prior call) ----------------
__global__ __launch_bounds__(512) void k_count(const void* __restrict__ ei, int nE) {
    int is64 = detect_is64(ei);
    int e = blockIdx.x * 512 + threadIdx.x;
    if (e < nE) atomicAdd(&g_deg[edge_at(ei, nE + e, is64)], 1);
}

// ---------------- dinv + cursor reset ----------------
__global__ __launch_bounds__(512) void k_dinv(int n) {
    int i = blockIdx.x * 512 + threadIdx.x;
    if (i < n) {
        g_dinv[i] = rsqrtf((float)(g_deg[i] + 1));  // +1 self loop
        g_cursor[i] = 0;
    }
}

// ---------------- bucket fill: no scan needed ----------------
__global__ __launch_bounds__(512) void k_fill(const void* __restrict__ ei, int nE) {
    int is64 = detect_is64(ei);
    int e = blockIdx.x * 512 + threadIdx.x;
    if (e < nE) {
        int r = edge_at(ei, e, is64);
        int c = edge_at(ei, nE + e, is64);
        int pos = atomicAdd(&g_cursor[c], 1);
        if (pos < BUCKET)
            g_edge[c * BUCKET + pos] = make_int2(r, __float_as_int(g_dinv[r] * g_dinv[c]));
    }
}

// ---------------- fp32x8 -> swizzled fp16 smem store ----------------
__device__ __forceinline__ void st_chunk_h(__half* S, int row, int chunk,
                                           float4 u, float4 v) {
    int4 pk;
    ((__half2*)&pk)[0] = __floats2half2_rn(u.x, u.y);
    ((__half2*)&pk)[1] = __floats2half2_rn(u.z, u.w);
    ((__half2*)&pk)[2] = __floats2half2_rn(v.x, v.y);
    ((__half2*)&pk)[3] = __floats2half2_rn(v.z, v.w);
    *(int4*)&S[swz(row, chunk * 8)] = pk;
}

// ---------------- mma mainloop: C[8][4] += As(64x128) @ Wh(128x128) ----------------
__device__ __forceinline__ void mma_tile(const __half* As, const __half* Wh,
                                         float C[8][4], int wr, int wc, int lane) {
    unsigned a_base = (unsigned)__cvta_generic_to_shared(As);
    unsigned w_base = (unsigned)__cvta_generic_to_shared(Wh);
#pragma unroll
    for (int ks = 0; ks < 8; ks++) {
        unsigned r0, r1, r2, r3;
        int arow = wr * 16 + (lane & 15);
        int acolh = ks * 16 + ((lane >> 4) << 3);
        unsigned a0, a1, a2, a3;
        LDSM_X4(a0, a1, a2, a3, a_base + swz(arow, acolh) * 2);
#pragma unroll
        for (int f2 = 0; f2 < 4; f2++) {
            int brow = ks * 16 + (lane & 15);
            int bcolh = wc * 64 + f2 * 16 + (((lane >> 4) & 1) << 3);
            LDSM_X4_T(r0, r1, r2, r3, w_base + swz(brow, bcolh) * 2);
            MMA16816(C[f2 * 2][0], C[f2 * 2][1], C[f2 * 2][2], C[f2 * 2][3],
                     a0, a1, a2, a3, r0, r1);
            MMA16816(C[f2 * 2 + 1][0], C[f2 * 2 + 1][1], C[f2 * 2 + 1][2], C[f2 * 2 + 1][3],
                     a0, a1, a2, a3, r2, r3);
        }
    }
}

// ---------------- GEMM layer 1: g_H = fp16(x @ W1)  (HMMA) ----------------
__global__ __launch_bounds__(256) void k_gemm1(const float* __restrict__ X,
                                               const float* __restrict__ W, int n) {
    __shared__ __half As[64 * 128];   // 16 KB
    __shared__ __half Wh[128 * 128];  // 32 KB
    int tid = threadIdx.x;
    int row0 = blockIdx.x * 64;

#pragma unroll
    for (int j = 0; j < 8; j++) {
        int task = tid + j * 256;
        int k = task >> 4, ch = task & 15;
        float4 u = *(const float4*)&W[(size_t)k * 128 + ch * 8];
        float4 v = *(const float4*)&W[(size_t)k * 128 + ch * 8 + 4];
        st_chunk_h(Wh, k, ch, u, v);
    }
#pragma unroll
    for (int j = 0; j < 4; j++) {
        int task = tid + j * 256;
        int r = task >> 4, ch = task & 15;
        float4 u = make_float4(0.f, 0.f, 0.f, 0.f), v = u;
        if (row0 + r < n) {
            u = *(const float4*)&X[(size_t)(row0 + r) * 128 + ch * 8];
            v = *(const float4*)&X[(size_t)(row0 + r) * 128 + ch * 8 + 4];
        }
        st_chunk_h(As, r, ch, u, v);
    }
    __syncthreads();

    int lane = tid & 31, wid = tid >> 5;
    int wr = wid >> 1, wc = wid & 1;
    float C[8][4];
#pragma unroll
    for (int f = 0; f < 8; f++)
#pragma unroll
        for (int q = 0; q < 4; q++) C[f][q] = 0.f;

    mma_tile(As, Wh, C, wr, wc, lane);

    int g = lane >> 2, t = lane & 3;
#pragma unroll
    for (int f = 0; f < 8; f++) {
        int col = wc * 64 + f * 8 + t * 2;
        int row = row0 + wr * 16 + g;
        if (row < n)
            *(__half2*)&g_H[(size_t)row * 128 + col] = __floats2half2_rn(C[f][0], C[f][1]);
        if (row + 8 < n)
            *(__half2*)&g_H[(size_t)(row + 8) * 128 + col] = __floats2half2_rn(C[f][2], C[f][3]);
    }
}

// ---------------- fp16-row gather (16 lanes per node, 8 ch per lane) ----------------
__device__ __forceinline__ void cvt8(int4 raw, float o[8]) {
    const __half2* h = (const __half2*)&raw;
    float2 a = __half22float2(h[0]), b = __half22float2(h[1]);
    float2 c = __half22float2(h[2]), d = __half22float2(h[3]);
    o[0] = a.x; o[1] = a.y; o[2] = b.x; o[3] = b.y;
    o[4] = c.x; o[5] = c.y; o[6] = d.x; o[7] = d.y;
}

__device__ __forceinline__ void gather_row_h(const __half* __restrict__ Hh,
                                             int node, int l, int deg, float f[8]) {
    float dn = g_dinv[node];
    float s0 = dn * dn;
    int4 raw = *(const int4*)(Hh + (size_t)node * CH + l * 8);
    float t[8]; cvt8(raw, t);
#pragma unroll
    for (int k = 0; k < 8; k++) f[k] = t[k] * s0;   // self loop

    int beg = node * BUCKET;
    int end = beg + (deg < BUCKET ? deg : BUCKET);
    int j = beg;
    for (; j + 4 <= end; j += 4) {
        int2 p0 = g_edge[j], p1 = g_edge[j + 1], p2 = g_edge[j + 2], p3 = g_edge[j + 3];
        int4 r0 = *(const int4*)(Hh + (size_t)p0.x * CH + l * 8);
        int4 r1 = *(const int4*)(Hh + (size_t)p1.x * CH + l * 8);
        int4 r2 = *(const int4*)(Hh + (size_t)p2.x * CH + l * 8);
        int4 r3 = *(const int4*)(Hh + (size_t)p3.x * CH + l * 8);
        float w0 = __int_as_float(p0.y), w1 = __int_as_float(p1.y);
        float w2 = __int_as_float(p2.y), w3 = __int_as_float(p3.y);
        float t0[8], t1[8], t2[8], t3[8];
        cvt8(r0, t0); cvt8(r1, t1); cvt8(r2, t2); cvt8(r3, t3);
#pragma unroll
        for (int k = 0; k < 8; k++)
            f[k] += t0[k] * w0 + t1[k] * w1 + t2[k] * w2 + t3[k] * w3;
    }
    for (; j < end; j++) {
        int2 p = g_edge[j];
        int4 r = *(const int4*)(Hh + (size_t)p.x * CH + l * 8);
        float w = __int_as_float(p.y);
        float t0[8]; cvt8(r, t0);
#pragma unroll
        for (int k = 0; k < 8; k++) f[k] += t0[k] * w;
    }
}

// ---------------- gather pass 1: hidden = fp16(relu(A_hat @ H + b1)) ----------------
__global__ __launch_bounds__(256) void k_gather0(const float* __restrict__ b1, int n) {
    int gt = blockIdx.x * 256 + threadIdx.x;
    int node = gt >> 4, l = gt & 15;
    if (node >= n) return;
    float f[8];
    gather_row_h(g_H, node, l, g_deg[node], f);
    float4 ba = *(const float4*)&b1[l * 8];
    float4 bb = *(const float4*)&b1[l * 8 + 4];
    f[0] = fmaxf(f[0] + ba.x, 0.f); f[1] = fmaxf(f[1] + ba.y, 0.f);
    f[2] = fmaxf(f[2] + ba.z, 0.f); f[3] = fmaxf(f[3] + ba.w, 0.f);
    f[4] = fmaxf(f[4] + bb.x, 0.f); f[5] = fmaxf(f[5] + bb.y, 0.f);
    f[6] = fmaxf(f[6] + bb.z, 0.f); f[7] = fmaxf(f[7] + bb.w, 0.f);
    int4 pk;
    ((__half2*)&pk)[0] = __floats2half2_rn(f[0], f[1]);
    ((__half2*)&pk)[1] = __floats2half2_rn(f[2], f[3]);
    ((__half2*)&pk)[2] = __floats2half2_rn(f[4], f[5]);
    ((__half2*)&pk)[3] = __floats2half2_rn(f[6], f[7]);
    *(int4*)&g_hidden[(size_t)node * CH + l * 8] = pk;
}

// ---------------- fused: As = fp16(A_hat @ hidden), HMMA, relu+bias, split ----------------
// Also restores g_deg to 0 for the next call (last reader).
__global__ __launch_bounds__(256) void k_gather_gemm2(const float* __restrict__ W2,
                                                      const float* __restrict__ W3,
                                                      const float* __restrict__ b2,
                                                      const float* __restrict__ b3,
                                                      float* __restrict__ out, int n) {
    __shared__ __half As[64 * 128];   // 16 KB
    __shared__ __half Wh[128 * 128];  // 32 KB: [W2 | W3]
    int tid = threadIdx.x;
    int node0 = blockIdx.x * 64;

#pragma unroll
    for (int j = 0; j < 8; j++) {
        int task = tid + j * 256;
        int k = task >> 4, ch = task & 15;
        const float* src = (ch < 8) ? &W2[(size_t)k * OUTC + ch * 8]
                                    : &W3[(size_t)k * OUTC + (ch - 8) * 8];
        float4 u = *(const float4*)&src[0];
        float4 v = *(const float4*)&src[4];
        st_chunk_h(Wh, k, ch, u, v);
    }

    int gg = tid >> 4, l = tid & 15;
#pragma unroll 1
    for (int i = 0; i < 4; i++) {
        int nl = gg * 4 + i;
        int node = node0 + nl;
        float f[8] = {0.f, 0.f, 0.f, 0.f, 0.f, 0.f, 0.f, 0.f};
        if (node < n) {
            int dg = g_deg[node];
            gather_row_h(g_hidden, node, l, dg, f);
            if (l == 0) g_deg[node] = 0;   // restore for next call
        }
        st_chunk_h(As, nl, l,
                   make_float4(f[0], f[1], f[2], f[3]),
                   make_float4(f[4], f[5], f[6], f[7]));
    }
    __syncthreads();

    int lane = tid & 31, wid = tid >> 5;
    int wr = wid >> 1, wc = wid & 1;
    float C[8][4];
#pragma unroll
    for (int f = 0; f < 8; f++)
#pragma unroll
        for (int q = 0; q < 4; q++) C[f][q] = 0.f;

    mma_tile(As, Wh, C, wr, wc, lane);

    const float* bb = wc ? b3 : b2;
    float* ob = wc ? out + (size_t)n * OUTC : out;
    int g = lane >> 2, t = lane & 3;
#pragma unroll
    for (int f = 0; f < 8; f++) {
        int col = f * 8 + t * 2;
        float bx = bb[col], by = bb[col + 1];
        int row = node0 + wr * 16 + g;
        if (row < n) {
            float2 v = make_float2(fmaxf(C[f][0] + bx, 0.f), fmaxf(C[f][1] + by, 0.f));
            *(float2*)&ob[(size_t)row * OUTC + col] = v;
        }
        if (row + 8 < n) {
            float2 v = make_float2(fmaxf(C[f][2] + bx, 0.f), fmaxf(C[f][3] + by, 0.f));
            *(float2*)&ob[(size_t)(row + 8) * OUTC + col] = v;
        }
    }
}

extern "C" void kernel_launch(void* const* d_in, const int* in_sizes, int n_in,
                              void* d_out, int out_size) {
    const float* x  = (const float*)d_in[0];
    const void*  ei = d_in[1];
    const float* W1 = (const float*)d_in[2];
    const float* b1 = (const float*)d_in[3];
    const float* W2 = (const float*)d_in[4];
    const float* b2 = (const float*)d_in[5];
    const float* W3 = (const float*)d_in[6];
    const float* b3 = (const float*)d_in[7];
    float* out = (float*)d_out;

    int nN = in_sizes[0] / CH;   // 50000
    int nE = in_sizes[1] / 2;    // 800000

    // one-time side-stream infra (identical launch sequence on every call)
    static cudaStream_t s2 = nullptr;
    static cudaEvent_t evFork = nullptr, evJoin = nullptr;
    if (s2 == nullptr) {
        cudaStreamCreateWithFlags(&s2, cudaStreamNonBlocking);
        cudaEventCreateWithFlags(&evFork, cudaEventDisableTiming);
        cudaEventCreateWithFlags(&evJoin, cudaEventDisableTiming);
    }

    // fork: gemm1 (independent of CSR build) on side stream
    cudaEventRecord(evFork, 0);
    cudaStreamWaitEvent(s2, evFork, 0);
    k_gemm1<<<(nN + 63) / 64, 256, 0, s2>>>(x, W1, nN);
    cudaEventRecord(evJoin, s2);

    // main stream: bucketed CSR build (no scan)
    k_count<<<(nE + 511) / 512, 512>>>(ei, nE);
    k_dinv <<<(nN + 511) / 512, 512>>>(nN);
    k_fill <<<(nE + 511) / 512, 512>>>(ei, nE);

    // join, then the dependent chain
    cudaStreamWaitEvent(0, evJoin, 0);
    k_gather0<<<(nN * 16 + 255) / 256, 256>>>(b1, nN);
    k_gather_gemm2<<<(nN + 63) / 64, 256>>>(W2, W3, b2, b3, out, nN);
}

// round 14
// speedup vs baseline: 1.0718x; 1.0718x over previous
#include <cuda_runtime.h>
#include <cuda_fp16.h>

#define MAX_NODES 50000
#define MAX_EDGES 800000
#define CH 128
#define OUTC 64

// ---- device scratch ----
__device__ __half g_H[MAX_NODES * CH];       // fp16(x @ W1)
__device__ __half g_hidden[MAX_NODES * CH];  // fp16(relu(A_hat@H+b1))
__device__ int    g_deg[MAX_NODES];          // self-restoring: zeroed by k_gather_gemm2
__device__ float  g_dinv[MAX_NODES];
// packed CSR by target node; edge payload {src:int, nrm:float}
__device__ int    g_ptr[MAX_NODES + 1];
__device__ int    g_cursor[MAX_NODES];
__device__ int2   g_edge[MAX_EDGES];
// decoupled-lookback scan state (flags re-zeroed by k_count block 0)
__device__ int    g_aggval[64];
__device__ int    g_aggflag[64];

// ---------------- mma / ldmatrix macros ----------------
#define LDSM_X4(r0, r1, r2, r3, addr) \
    asm volatile("ldmatrix.sync.aligned.m8n8.x4.shared.b16 {%0,%1,%2,%3}, [%4];" \
                 : "=r"(r0), "=r"(r1), "=r"(r2), "=r"(r3) : "r"(addr))
#define LDSM_X4_T(r0, r1, r2, r3, addr) \
    asm volatile("ldmatrix.sync.aligned.m8n8.x4.trans.shared.b16 {%0,%1,%2,%3}, [%4];" \
                 : "=r"(r0), "=r"(r1), "=r"(r2), "=r"(r3) : "r"(addr))
#define MMA16816(c0, c1, c2, c3, a0, a1, a2, a3, b0, b1) \
    asm volatile("mma.sync.aligned.m16n8k16.row.col.f32.f16.f16.f32 " \
                 "{%0,%1,%2,%3}, {%4,%5,%6,%7}, {%8,%9}, {%0,%1,%2,%3};" \
                 : "+f"(c0), "+f"(c1), "+f"(c2), "+f"(c3) \
                 : "r"(a0), "r"(a1), "r"(a2), "r"(a3), "r"(b0), "r"(b1))

// XOR swizzle for 256B rows (128 halves): conflict-free ldmatrix.
__device__ __forceinline__ int swz(int row, int colh) {
    int chunk = colh >> 3;
    chunk = (chunk & 8) | ((chunk ^ row) & 7);
    return row * 128 + chunk * 8 + (colh & 7);
}

// Per-block int64-vs-int32 edge dtype detection (odd words all zero => int64).
__device__ __forceinline__ int detect_is64(const void* ei) {
    __shared__ int s_is64;
    if (threadIdx.x < 32) {
        int w = ((const int*)ei)[2 * threadIdx.x + 1];
        unsigned m = __ballot_sync(~0u, w == 0);
        if (threadIdx.x == 0) s_is64 = (m == ~0u);
    }
    __syncthreads();
    return s_is64;
}

__device__ __forceinline__ int edge_at(const void* ei, int i, int is64) {
    if (is64) return (int)((const long long*)ei)[i];
    return ((const int*)ei)[i];
}

// ---------------- degree count (g_deg zeroed by load-init / previous call) ----------------
// Block 0 also resets the scan lookback flags (consumed only by k_scan, later).
__global__ __launch_bounds__(512) void k_count(const void* __restrict__ ei, int nE) {
    if (blockIdx.x == 0 && threadIdx.x < 64) g_aggflag[threadIdx.x] = 0;
    int is64 = detect_is64(ei);
    int e = blockIdx.x * 512 + threadIdx.x;
    if (e < nE) atomicAdd(&g_deg[edge_at(ei, nE + e, is64)], 1);
}

// ---------------- single-pass scan (decoupled lookback, <=64 blocks) ----------------
// Fuses dinv computation and cursor init.
__global__ __launch_bounds__(1024) void k_scan(int n) {
    __shared__ int wsum[32];
    __shared__ int s_off;
    int b = blockIdx.x;
    int i = b * 1024 + threadIdx.x;
    int lane = threadIdx.x & 31, wid = threadIdx.x >> 5;
    int d = (i < n) ? g_deg[i] : 0;
    if (i < n) g_dinv[i] = rsqrtf((float)(d + 1));   // +1 self loop
    int s = d;
#pragma unroll
    for (int o = 1; o < 32; o <<= 1) {
        int t = __shfl_up_sync(~0u, s, o);
        if (lane >= o) s += t;
    }
    if (lane == 31) wsum[wid] = s;
    __syncthreads();
    if (wid == 0) {
        int ws = wsum[lane];
#pragma unroll
        for (int o = 1; o < 32; o <<= 1) {
            int t = __shfl_up_sync(~0u, ws, o);
            if (lane >= o) ws += t;
        }
        wsum[lane] = ws;
    }
    __syncthreads();
    int incl = s + (wid > 0 ? wsum[wid - 1] : 0);

    if (threadIdx.x == 1023) {
        g_aggval[b] = incl;
        __threadfence();
        atomicExch(&g_aggflag[b], 1);
    }
    if (threadIdx.x < 32) {
        int acc = 0;
        for (int p = lane; p < b; p += 32) {
            while (atomicAdd(&g_aggflag[p], 0) == 0) {}
            acc += atomicAdd(&g_aggval[p], 0);
        }
#pragma unroll
        for (int o = 16; o; o >>= 1) acc += __shfl_down_sync(~0u, acc, o);
        if (lane == 0) s_off = acc;
    }
    __syncthreads();
    if (i < n) {
        int p1 = incl + s_off;
        g_ptr[i + 1] = p1;
        g_cursor[i] = p1 - d;
    }
    if (i == 0) g_ptr[0] = 0;
}

__global__ __launch_bounds__(512) void k_fill(const void* __restrict__ ei, int nE) {
    int is64 = detect_is64(ei);
    int e = blockIdx.x * 512 + threadIdx.x;
    if (e < nE) {
        int r = edge_at(ei, e, is64);
        int c = edge_at(ei, nE + e, is64);
        int pos = atomicAdd(&g_cursor[c], 1);
        g_edge[pos] = make_int2(r, __float_as_int(g_dinv[r] * g_dinv[c]));
    }
}

// ---------------- fp32x8 -> swizzled fp16 smem store ----------------
__device__ __forceinline__ void st_chunk_h(__half* S, int row, int chunk,
                                           float4 u, float4 v) {
    int4 pk;
    ((__half2*)&pk)[0] = __floats2half2_rn(u.x, u.y);
    ((__half2*)&pk)[1] = __floats2half2_rn(u.z, u.w);
    ((__half2*)&pk)[2] = __floats2half2_rn(v.x, v.y);
    ((__half2*)&pk)[3] = __floats2half2_rn(v.z, v.w);
    *(int4*)&S[swz(row, chunk * 8)] = pk;
}

// ---------------- mma mainloop: C[8][4] += As(64x128) @ Wh(128x128) ----------------
__device__ __forceinline__ void mma_tile(const __half* As, const __half* Wh,
                                         float C[8][4], int wr, int wc, int lane) {
    unsigned a_base = (unsigned)__cvta_generic_to_shared(As);
    unsigned w_base = (unsigned)__cvta_generic_to_shared(Wh);
#pragma unroll
    for (int ks = 0; ks < 8; ks++) {
        unsigned r0, r1, r2, r3;
        int arow = wr * 16 + (lane & 15);
        int acolh = ks * 16 + ((lane >> 4) << 3);
        unsigned a0, a1, a2, a3;
        LDSM_X4(a0, a1, a2, a3, a_base + swz(arow, acolh) * 2);
#pragma unroll
        for (int f2 = 0; f2 < 4; f2++) {
            int brow = ks * 16 + (lane & 15);
            int bcolh = wc * 64 + f2 * 16 + (((lane >> 4) & 1) << 3);
            LDSM_X4_T(r0, r1, r2, r3, w_base + swz(brow, bcolh) * 2);
            MMA16816(C[f2 * 2][0], C[f2 * 2][1], C[f2 * 2][2], C[f2 * 2][3],
                     a0, a1, a2, a3, r0, r1);
            MMA16816(C[f2 * 2 + 1][0], C[f2 * 2 + 1][1], C[f2 * 2 + 1][2], C[f2 * 2 + 1][3],
                     a0, a1, a2, a3, r2, r3);
        }
    }
}

// ---------------- GEMM layer 1: g_H = fp16(x @ W1)  (HMMA) ----------------
__global__ __launch_bounds__(256) void k_gemm1(const float* __restrict__ X,
                                               const float* __restrict__ W, int n) {
    __shared__ __half As[64 * 128];   // 16 KB
    __shared__ __half Wh[128 * 128];  // 32 KB
    int tid = threadIdx.x;
    int row0 = blockIdx.x * 64;

#pragma unroll
    for (int j = 0; j < 8; j++) {
        int task = tid + j * 256;
        int k = task >> 4, ch = task & 15;
        float4 u = *(const float4*)&W[(size_t)k * 128 + ch * 8];
        float4 v = *(const float4*)&W[(size_t)k * 128 + ch * 8 + 4];
        st_chunk_h(Wh, k, ch, u, v);
    }
#pragma unroll
    for (int j = 0; j < 4; j++) {
        int task = tid + j * 256;
        int r = task >> 4, ch = task & 15;
        float4 u = make_float4(0.f, 0.f, 0.f, 0.f), v = u;
        if (row0 + r < n) {
            u = *(const float4*)&X[(size_t)(row0 + r) * 128 + ch * 8];
            v = *(const float4*)&X[(size_t)(row0 + r) * 128 + ch * 8 + 4];
        }
        st_chunk_h(As, r, ch, u, v);
    }
    __syncthreads();

    int lane = tid & 31, wid = tid >> 5;
    int wr = wid >> 1, wc = wid & 1;
    float C[8][4];
#pragma unroll
    for (int f = 0; f < 8; f++)
#pragma unroll
        for (int q = 0; q < 4; q++) C[f][q] = 0.f;

    mma_tile(As, Wh, C, wr, wc, lane);

    int g = lane >> 2, t = lane & 3;
#pragma unroll
    for (int f = 0; f < 8; f++) {
        int col = wc * 64 + f * 8 + t * 2;
        int row = row0 + wr * 16 + g;
        if (row < n)
            *(__half2*)&g_H[(size_t)row * 128 + col] = __floats2half2_rn(C[f][0], C[f][1]);
        if (row + 8 < n)
            *(__half2*)&g_H[(size_t)(row + 8) * 128 + col] = __floats2half2_rn(C[f][2], C[f][3]);
    }
}

// ---------------- fp16-row gather (16 lanes per node, 8 ch per lane) ----------------
__device__ __forceinline__ void cvt8(int4 raw, float o[8]) {
    const __half2* h = (const __half2*)&raw;
    float2 a = __half22float2(h[0]), b = __half22float2(h[1]);
    float2 c = __half22float2(h[2]), d = __half22float2(h[3]);
    o[0] = a.x; o[1] = a.y; o[2] = b.x; o[3] = b.y;
    o[4] = c.x; o[5] = c.y; o[6] = d.x; o[7] = d.y;
}

__device__ __forceinline__ void gather_row_h(const __half* __restrict__ Hh,
                                             int node, int l, float f[8]) {
    float dn = g_dinv[node];
    float s0 = dn * dn;
    int4 raw = *(const int4*)(Hh + (size_t)node * CH + l * 8);
    float t[8]; cvt8(raw, t);
#pragma unroll
    for (int k = 0; k < 8; k++) f[k] = t[k] * s0;   // self loop

    int beg = g_ptr[node], end = g_ptr[node + 1];
    int j = beg;
    for (; j + 4 <= end; j += 4) {
        int2 p0 = g_edge[j], p1 = g_edge[j + 1], p2 = g_edge[j + 2], p3 = g_edge[j + 3];
        int4 r0 = *(const int4*)(Hh + (size_t)p0.x * CH + l * 8);
        int4 r1 = *(const int4*)(Hh + (size_t)p1.x * CH + l * 8);
        int4 r2 = *(const int4*)(Hh + (size_t)p2.x * CH + l * 8);
        int4 r3 = *(const int4*)(Hh + (size_t)p3.x * CH + l * 8);
        float w0 = __int_as_float(p0.y), w1 = __int_as_float(p1.y);
        float w2 = __int_as_float(p2.y), w3 = __int_as_float(p3.y);
        float t0[8], t1[8], t2[8], t3[8];
        cvt8(r0, t0); cvt8(r1, t1); cvt8(r2, t2); cvt8(r3, t3);
#pragma unroll
        for (int k = 0; k < 8; k++)
            f[k] += t0[k] * w0 + t1[k] * w1 + t2[k] * w2 + t3[k] * w3;
    }
    for (; j < end; j++) {
        int2 p = g_edge[j];
        int4 r = *(const int4*)(Hh + (size_t)p.x * CH + l * 8);
        float w = __int_as_float(p.y);
        float t0[8]; cvt8(r, t0);
#pragma unroll
        for (int k = 0; k < 8; k++) f[k] += t0[k] * w;
    }
}

// ---------------- gather pass 1: hidden = fp16(relu(A_hat @ H + b1)) ----------------
__global__ __launch_bounds__(256) void k_gather0(const float* __restrict__ b1, int n) {
    int gt = blockIdx.x * 256 + threadIdx.x;
    int node = gt >> 4, l = gt & 15;
    if (node >= n) return;
    float f[8];
    gather_row_h(g_H, node, l, f);
    float4 ba = *(const float4*)&b1[l * 8];
    float4 bb = *(const float4*)&b1[l * 8 + 4];
    f[0] = fmaxf(f[0] + ba.x, 0.f); f[1] = fmaxf(f[1] + ba.y, 0.f);
    f[2] = fmaxf(f[2] + ba.z, 0.f); f[3] = fmaxf(f[3] + ba.w, 0.f);
    f[4] = fmaxf(f[4] + bb.x, 0.f); f[5] = fmaxf(f[5] + bb.y, 0.f);
    f[6] = fmaxf(f[6] + bb.z, 0.f); f[7] = fmaxf(f[7] + bb.w, 0.f);
    int4 pk;
    ((__half2*)&pk)[0] = __floats2half2_rn(f[0], f[1]);
    ((__half2*)&pk)[1] = __floats2half2_rn(f[2], f[3]);
    ((__half2*)&pk)[2] = __floats2half2_rn(f[4], f[5]);
    ((__half2*)&pk)[3] = __floats2half2_rn(f[6], f[7]);
    *(int4*)&g_hidden[(size_t)node * CH + l * 8] = pk;
}

// ---------------- fused: As = fp16(A_hat @ hidden), HMMA, relu+bias, split ----------------
// Also restores g_deg to 0 for the next call (runs after k_scan, its last reader).
__global__ __launch_bounds__(256) void k_gather_gemm2(const float* __restrict__ W2,
                                                      const float* __restrict__ W3,
                                                      const float* __restrict__ b2,
                                                      const float* __restrict__ b3,
                                                      float* __restrict__ out, int n) {
    __shared__ __half As[64 * 128];   // 16 KB
    __shared__ __half Wh[128 * 128];  // 32 KB: [W2 | W3]
    int tid = threadIdx.x;
    int node0 = blockIdx.x * 64;

    // restore g_deg for next replay (this block's 64 nodes)
    if (tid < 64 && node0 + tid < n) g_deg[node0 + tid] = 0;

#pragma unroll
    for (int j = 0; j < 8; j++) {
        int task = tid + j * 256;
        int k = task >> 4, ch = task & 15;
        const float* src = (ch < 8) ? &W2[(size_t)k * OUTC + ch * 8]
                                    : &W3[(size_t)k * OUTC + (ch - 8) * 8];
        float4 u = *(const float4*)&src[0];
        float4 v = *(const float4*)&src[4];
        st_chunk_h(Wh, k, ch, u, v);
    }

    int gg = tid >> 4, l = tid & 15;
#pragma unroll 1
    for (int i = 0; i < 4; i++) {
        int nl = gg * 4 + i;
        int node = node0 + nl;
        float f[8] = {0.f, 0.f, 0.f, 0.f, 0.f, 0.f, 0.f, 0.f};
        if (node < n) gather_row_h(g_hidden, node, l, f);
        st_chunk_h(As, nl, l,
                   make_float4(f[0], f[1], f[2], f[3]),
                   make_float4(f[4], f[5], f[6], f[7]));
    }
    __syncthreads();

    int lane = tid & 31, wid = tid >> 5;
    int wr = wid >> 1, wc = wid & 1;
    float C[8][4];
#pragma unroll
    for (int f = 0; f < 8; f++)
#pragma unroll
        for (int q = 0; q < 4; q++) C[f][q] = 0.f;

    mma_tile(As, Wh, C, wr, wc, lane);

    const float* bb = wc ? b3 : b2;
    float* ob = wc ? out + (size_t)n * OUTC : out;
    int g = lane >> 2, t = lane & 3;
#pragma unroll
    for (int f = 0; f < 8; f++) {
        int col = f * 8 + t * 2;
        float bx = bb[col], by = bb[col + 1];
        int row = node0 + wr * 16 + g;
        if (row < n) {
            float2 v = make_float2(fmaxf(C[f][0] + bx, 0.f), fmaxf(C[f][1] + by, 0.f));
            *(float2*)&ob[(size_t)row * OUTC + col] = v;
        }
        if (row + 8 < n) {
            float2 v = make_float2(fmaxf(C[f][2] + bx, 0.f), fmaxf(C[f][3] + by, 0.f));
            *(float2*)&ob[(size_t)(row + 8) * OUTC + col] = v;
        }
    }
}

extern "C" void kernel_launch(void* const* d_in, const int* in_sizes, int n_in,
                              void* d_out, int out_size) {
    const float* x  = (const float*)d_in[0];
    const void*  ei = d_in[1];
    const float* W1 = (const float*)d_in[2];
    const float* b1 = (const float*)d_in[3];
    const float* W2 = (const float*)d_in[4];
    const float* b2 = (const float*)d_in[5];
    const float* W3 = (const float*)d_in[6];
    const float* b3 = (const float*)d_in[7];
    float* out = (float*)d_out;

    int nN = in_sizes[0] / CH;   // 50000
    int nE = in_sizes[1] / 2;    // 800000
    int nb = (nN + 1023) / 1024;

    // one-time side-stream infra (identical launch sequence on every call)
    static cudaStream_t s2 = nullptr;
    static cudaEvent_t evFork = nullptr, evJoin = nullptr;
    if (s2 == nullptr) {
        cudaStreamCreateWithFlags(&s2, cudaStreamNonBlocking);
        cudaEventCreateWithFlags(&evFork, cudaEventDisableTiming);
        cudaEventCreateWithFlags(&evJoin, cudaEventDisableTiming);
    }

    // fork: gemm1 (independent of CSR build) on side stream
    cudaEventRecord(evFork, 0);
    cudaStreamWaitEvent(s2, evFork, 0);
    k_gemm1<<<(nN + 63) / 64, 256, 0, s2>>>(x, W1, nN);
    cudaEventRecord(evJoin, s2);

    // main stream: packed CSR build (count also resets scan flags)
    k_count<<<(nE + 511) / 512, 512>>>(ei, nE);
    k_scan <<<nb, 1024>>>(nN);
    k_fill <<<(nE + 511) / 512, 512>>>(ei, nE);

    // join, then the dependent chain
    cudaStreamWaitEvent(0, evJoin, 0);
    k_gather0<<<(nN * 16 + 255) / 256, 256>>>(b1, nN);
    k_gather_gemm2<<<(nN + 63) / 64, 256>>>(W2, W3, b2, b3, out, nN);
}